// round 2
// baseline (speedup 1.0000x reference)
#include <cuda_runtime.h>

typedef unsigned long long ull;

#define DIM 512
#define NX  1024
#define NY  1024

// Scratch (allocation-free rule: static __device__ arrays)
__device__ float g_hx[NX * DIM];
__device__ float g_hy[NY * DIM];

// ---------- packed f32x2 helpers (FFMA2/FADD2 only exist via PTX) ----------
__device__ __forceinline__ ull f2_fma(ull a, ull b, ull c) {
    ull r;
    asm("fma.rn.f32x2 %0, %1, %2, %3;" : "=l"(r) : "l"(a), "l"(b), "l"(c));
    return r;
}
__device__ __forceinline__ ull f2_add(ull a, ull b) {
    ull r;
    asm("add.rn.f32x2 %0, %1, %2;" : "=l"(r) : "l"(a), "l"(b));
    return r;
}
__device__ __forceinline__ ull f2_relu(ull s) {
    float lo, hi;
    asm("mov.b64 {%0, %1}, %2;" : "=f"(lo), "=f"(hi) : "l"(s));
    lo = fmaxf(lo, 0.0f);
    hi = fmaxf(hi, 0.0f);
    ull r;
    asm("mov.b64 %0, {%1, %2};" : "=l"(r) : "f"(lo), "f"(hi));
    return r;
}
__device__ __forceinline__ float f2_sum(ull s) {
    float lo, hi;
    asm("mov.b64 {%0, %1}, %2;" : "=f"(lo), "=f"(hi) : "l"(s));
    return lo + hi;
}

// ============================================================================
// Phase 1: hx = x @ W1[:DIM], hy = y @ W1[DIM:]   (z = 0 / 1)
// CTA tile 128(i) x 64(k), Kc = 16, 256 threads, thread tile 8x4.
// d-pairs packed: acc.lo accumulates even d, acc.hi odd d; summed at the end.
// ============================================================================
__global__ void __launch_bounds__(256) gemm_kernel(
    const float* __restrict__ x, const float* __restrict__ y,
    const float* __restrict__ W1)
{
    __shared__ float2 xsp[8][129];  // [d-pair][i] for 128 i
    __shared__ float2 wsp[8][65];   // [d-pair][k] for 64 k

    const int z = blockIdx.z;
    const float* src = z ? y : x;
    const float* W   = W1 + z * (DIM * DIM);
    float* dst       = z ? g_hy : g_hx;

    const int tid = threadIdx.x;
    const int tx  = tid & 15;   // k lane
    const int ty  = tid >> 4;   // i lane
    const int i0  = blockIdx.y * 128;
    const int k0  = blockIdx.x * 64;

    ull acc[8][4] = {};

    for (int dc = 0; dc < DIM; dc += 16) {
        // x tile: 128 rows x 16 d = 512 float4, 2 per thread
        #pragma unroll
        for (int t = 0; t < 2; t++) {
            int idx = tid + t * 256;
            int row = idx >> 2;
            int c4  = idx & 3;
            float4 v = *(const float4*)&src[(i0 + row) * DIM + dc + c4 * 4];
            xsp[c4 * 2 + 0][row] = make_float2(v.x, v.y);
            xsp[c4 * 2 + 1][row] = make_float2(v.z, v.w);
        }
        // W tile: 16 d-rows x 64 k; threads 0..127 each load two rows of 4 k
        if (tid < 128) {
            int dp = tid >> 4;
            int c4 = tid & 15;
            const float* wp = &W[(dc + 2 * dp) * DIM + k0 + c4 * 4];
            float4 va = *(const float4*)wp;
            float4 vb = *(const float4*)(wp + DIM);
            wsp[dp][c4 * 4 + 0] = make_float2(va.x, vb.x);
            wsp[dp][c4 * 4 + 1] = make_float2(va.y, vb.y);
            wsp[dp][c4 * 4 + 2] = make_float2(va.z, vb.z);
            wsp[dp][c4 * 4 + 3] = make_float2(va.w, vb.w);
        }
        __syncthreads();
        #pragma unroll
        for (int dp = 0; dp < 8; dp++) {
            ull ap[8], bp[4];
            #pragma unroll
            for (int q = 0; q < 8; q++)
                ap[q] = *(const ull*)&xsp[dp][ty + 16 * q];   // broadcast
            #pragma unroll
            for (int q = 0; q < 4; q++)
                bp[q] = *(const ull*)&wsp[dp][tx + 16 * q];   // lane-contiguous
            #pragma unroll
            for (int a = 0; a < 8; a++)
                #pragma unroll
                for (int b = 0; b < 4; b++)
                    acc[a][b] = f2_fma(ap[a], bp[b], acc[a][b]);
        }
        __syncthreads();
    }
    #pragma unroll
    for (int a = 0; a < 8; a++)
        #pragma unroll
        for (int b = 0; b < 4; b++)
            dst[(i0 + ty + 16 * a) * DIM + k0 + tx + 16 * b] = f2_sum(acc[a][b]);
}

// ============================================================================
// Phase 2: out[i,j] = sum_k w2[k] * relu(hx[i,k] + hy[j,k])
// CTA tile 128(i) x 64(j), Kc = 32, 256 threads, thread tile 8x4.
// Packed over k: FADD2 + 2xFMNMX + FFMA2 per 2 k's per output.
// ============================================================================
__global__ void __launch_bounds__(256) pair_kernel(
    const float* __restrict__ W2, float* __restrict__ out)
{
    __shared__ float2 hxsp[16][129];   // [k-pair][i]
    __shared__ float2 hysp[16][65];    // [k-pair][j]
    __shared__ float2 w2s[DIM / 2];

    const int tid = threadIdx.x;
    const int tx  = tid & 15;   // j lane
    const int ty  = tid >> 4;   // i lane
    const int i0  = blockIdx.y * 128;
    const int j0  = blockIdx.x * 64;

    if (tid < DIM / 2) w2s[tid] = ((const float2*)W2)[tid];

    ull acc[8][4] = {};

    for (int kc = 0; kc < DIM; kc += 32) {
        // hx tile: 128 rows x 32 k = 1024 float4, 4 per thread
        #pragma unroll
        for (int t = 0; t < 4; t++) {
            int idx = tid + t * 256;
            int row = idx >> 3;
            int c4  = idx & 7;
            float4 v = *(const float4*)&g_hx[(i0 + row) * DIM + kc + c4 * 4];
            hxsp[c4 * 2 + 0][row] = make_float2(v.x, v.y);
            hxsp[c4 * 2 + 1][row] = make_float2(v.z, v.w);
        }
        // hy tile: 64 rows x 32 k = 512 float4, 2 per thread
        #pragma unroll
        for (int t = 0; t < 2; t++) {
            int idx = tid + t * 256;
            int row = idx >> 3;
            int c4  = idx & 7;
            float4 v = *(const float4*)&g_hy[(j0 + row) * DIM + kc + c4 * 4];
            hysp[c4 * 2 + 0][row] = make_float2(v.x, v.y);
            hysp[c4 * 2 + 1][row] = make_float2(v.z, v.w);
        }
        __syncthreads();
        #pragma unroll 4
        for (int dp = 0; dp < 16; dp++) {
            ull w2k = *(const ull*)&w2s[(kc >> 1) + dp];
            ull ap[8], bp[4];
            #pragma unroll
            for (int q = 0; q < 8; q++)
                ap[q] = *(const ull*)&hxsp[dp][ty + 16 * q];   // broadcast
            #pragma unroll
            for (int q = 0; q < 4; q++)
                bp[q] = *(const ull*)&hysp[dp][tx + 16 * q];   // lane-contiguous
            #pragma unroll
            for (int a = 0; a < 8; a++)
                #pragma unroll
                for (int b = 0; b < 4; b++)
                    acc[a][b] = f2_fma(f2_relu(f2_add(ap[a], bp[b])), w2k, acc[a][b]);
        }
        __syncthreads();
    }

    #pragma unroll
    for (int a = 0; a < 8; a++)
        #pragma unroll
        for (int b = 0; b < 4; b++)
            out[(i0 + ty + 16 * a) * NY + (j0 + tx + 16 * b)] = f2_sum(acc[a][b]);
}

extern "C" void kernel_launch(void* const* d_in, const int* in_sizes, int n_in,
                              void* d_out, int out_size) {
    const float* x  = (const float*)d_in[0];
    const float* y  = (const float*)d_in[1];
    const float* W1 = (const float*)d_in[2];
    const float* W2 = (const float*)d_in[3];
    // d_in[4] = is_pairwise (int32) — dataset fixes it to 0 (out_size == NX*NY)
    float* out = (float*)d_out;

    dim3 g1(DIM / 64, NX / 128, 2);   // 8 x 8 x 2 = 128 CTAs
    gemm_kernel<<<g1, 256>>>(x, y, W1);

    dim3 g2(NY / 64, NX / 128);       // 16 x 8 = 128 CTAs
    pair_kernel<<<g2, 256>>>(W2, out);
}

// round 5
// speedup vs baseline: 1.1373x; 1.1373x over previous
#include <cuda_runtime.h>

typedef unsigned long long ull;

#define DIM 512
#define NX  1024
#define NY  1024

// Scratch (allocation-free rule: static __device__ arrays)
__device__ float g_hx[NX * DIM];
__device__ float g_hy[NY * DIM];

// ---------- packed f32x2 helpers ----------
__device__ __forceinline__ ull f2_fma(ull a, ull b, ull c) {
    ull r;
    asm("fma.rn.f32x2 %0, %1, %2, %3;" : "=l"(r) : "l"(a), "l"(b), "l"(c));
    return r;
}
__device__ __forceinline__ ull f2_add(ull a, ull b) {
    ull r;
    asm("add.rn.f32x2 %0, %1, %2;" : "=l"(r) : "l"(a), "l"(b));
    return r;
}
__device__ __forceinline__ ull f2_relu(ull s) {
    float lo, hi;
    asm("mov.b64 {%0, %1}, %2;" : "=f"(lo), "=f"(hi) : "l"(s));
    lo = fmaxf(lo, 0.0f);
    hi = fmaxf(hi, 0.0f);
    ull r;
    asm("mov.b64 %0, {%1, %2};" : "=l"(r) : "f"(lo), "f"(hi));
    return r;
}
__device__ __forceinline__ float f2_sum(ull s) {
    float lo, hi;
    asm("mov.b64 {%0, %1}, %2;" : "=f"(lo), "=f"(hi) : "l"(s));
    return lo + hi;
}

// ============================================================================
// Phase 1: hx = x @ W1[:DIM], hy = y @ W1[DIM:]   (z = 0 / 1)
// CTA tile 64(i) x 64(k), Dc = 16, 256 threads, thread tile 4x4, double-buffered.
// d-pairs packed into f32x2 lanes; summed at the end.
// ============================================================================
__global__ void __launch_bounds__(256, 3) gemm_kernel(
    const float* __restrict__ x, const float* __restrict__ y,
    const float* __restrict__ W1)
{
    __shared__ float2 xsp[2][8][65];  // [buf][d-pair][i 0..63]
    __shared__ float2 wsp[2][8][65];  // [buf][d-pair][k 0..63]

    const int z = blockIdx.z;
    const float* src = z ? y : x;
    const float* W   = W1 + z * (DIM * DIM);
    float* dst       = z ? g_hy : g_hx;

    const int tid = threadIdx.x;
    const int tx  = tid & 15;   // k lane
    const int ty  = tid >> 4;   // i lane
    const int i0  = blockIdx.y * 64;
    const int k0  = blockIdx.x * 64;

    // x tile load: 64 rows x 4 float4-cols, 1 float4/thread (coalesced 64B runs)
    const int xrow = tid >> 2, xc4 = tid & 3;
    // W tile load: 16 d-rows x 16 float4-cols, 1 float4/thread (coalesced rows)
    const int wrow = ty, wc4 = tx;

    const float* xg = src + (i0 + xrow) * DIM + xc4 * 4;   // advance by +16 per iter
    const float* wg = W + wrow * DIM + k0 + wc4 * 4;       // advance by +16*DIM per iter

    float4 px = *(const float4*)xg;
    float4 pw = *(const float4*)wg;

    ull acc[4][4] = {};

    const int NIT = DIM / 16;
    for (int it = 0; it < NIT; ++it) {
        const int cur = it & 1;
        // store prefetched chunk into smem[cur]
        xsp[cur][xc4 * 2 + 0][xrow] = make_float2(px.x, px.y);
        xsp[cur][xc4 * 2 + 1][xrow] = make_float2(px.z, px.w);
        {
            float* wb = (float*)&wsp[cur][wrow >> 1][0] + (wrow & 1);
            wb[(wc4 * 4 + 0) * 2] = pw.x;
            wb[(wc4 * 4 + 1) * 2] = pw.y;
            wb[(wc4 * 4 + 2) * 2] = pw.z;
            wb[(wc4 * 4 + 3) * 2] = pw.w;
        }
        // prefetch next chunk (lands while we compute)
        if (it + 1 < NIT) {
            px = *(const float4*)(xg + (it + 1) * 16);
            pw = *(const float4*)(wg + (it + 1) * 16 * DIM);
        }
        __syncthreads();
        #pragma unroll
        for (int dp = 0; dp < 8; ++dp) {
            ull ap[4], bp[4];
            #pragma unroll
            for (int q = 0; q < 4; ++q)
                ap[q] = *(const ull*)&xsp[cur][dp][ty + 16 * q];   // broadcast
            #pragma unroll
            for (int q = 0; q < 4; ++q)
                bp[q] = *(const ull*)&wsp[cur][dp][tx + 16 * q];   // lane-contiguous
            #pragma unroll
            for (int a = 0; a < 4; ++a)
                #pragma unroll
                for (int b = 0; b < 4; ++b)
                    acc[a][b] = f2_fma(ap[a], bp[b], acc[a][b]);
        }
        __syncthreads();
    }
    #pragma unroll
    for (int a = 0; a < 4; ++a)
        #pragma unroll
        for (int b = 0; b < 4; ++b)
            dst[(i0 + ty + 16 * a) * DIM + k0 + tx + 16 * b] = f2_sum(acc[a][b]);
}

// ============================================================================
// Phase 2: out[i,j] = sum_k w2[k] * relu(hx[i,k] + hy[j,k])
// CTA tile 64(i) x 64(j), Kc = 32, 256 threads, thread tile 4x4, double-buffered.
// ============================================================================
__global__ void __launch_bounds__(256, 3) pair_kernel(
    const float* __restrict__ W2, float* __restrict__ out)
{
    __shared__ float2 hxs[2][16][65];   // [buf][k-pair][i]
    __shared__ float2 hys[2][16][65];   // [buf][k-pair][j]
    __shared__ float2 w2s[DIM / 2];

    const int tid = threadIdx.x;
    const int tx  = tid & 15;   // j lane
    const int ty  = tid >> 4;   // i lane
    const int i0  = blockIdx.y * 64;
    const int j0  = blockIdx.x * 64;

    w2s[tid] = ((const float2*)W2)[tid];   // 256 float2 = DIM/2, read after first sync

    // tile loads: 64 rows x 8 float4-cols = 512 float4 each; 2/thread
    const int hr0 = tid >> 3;          // t=0 row (0..31)
    const int hc4 = tid & 7;
    const float* hxg = g_hx + (i0 + hr0) * DIM + hc4 * 4;
    const float* hyg = g_hy + (j0 + hr0) * DIM + hc4 * 4;

    float4 pxa = *(const float4*)hxg;
    float4 pxb = *(const float4*)(hxg + 32 * DIM);
    float4 pya = *(const float4*)hyg;
    float4 pyb = *(const float4*)(hyg + 32 * DIM);

    ull acc[4][4] = {};

    const int NIT = DIM / 32;
    for (int it = 0; it < NIT; ++it) {
        const int cur = it & 1;
        // store prefetched chunk into smem[cur]
        hxs[cur][hc4 * 2 + 0][hr0]      = make_float2(pxa.x, pxa.y);
        hxs[cur][hc4 * 2 + 1][hr0]      = make_float2(pxa.z, pxa.w);
        hxs[cur][hc4 * 2 + 0][hr0 + 32] = make_float2(pxb.x, pxb.y);
        hxs[cur][hc4 * 2 + 1][hr0 + 32] = make_float2(pxb.z, pxb.w);
        hys[cur][hc4 * 2 + 0][hr0]      = make_float2(pya.x, pya.y);
        hys[cur][hc4 * 2 + 1][hr0]      = make_float2(pya.z, pya.w);
        hys[cur][hc4 * 2 + 0][hr0 + 32] = make_float2(pyb.x, pyb.y);
        hys[cur][hc4 * 2 + 1][hr0 + 32] = make_float2(pyb.z, pyb.w);
        // prefetch next chunk
        if (it + 1 < NIT) {
            const int off = (it + 1) * 32;
            pxa = *(const float4*)(hxg + off);
            pxb = *(const float4*)(hxg + off + 32 * DIM);
            pya = *(const float4*)(hyg + off);
            pyb = *(const float4*)(hyg + off + 32 * DIM);
        }
        __syncthreads();
        #pragma unroll 4
        for (int dp = 0; dp < 16; ++dp) {
            ull w2k = *(const ull*)&w2s[it * 16 + dp];
            ull ap[4], bp[4];
            #pragma unroll
            for (int q = 0; q < 4; ++q)
                ap[q] = *(const ull*)&hxs[cur][dp][ty + 16 * q];   // broadcast
            #pragma unroll
            for (int q = 0; q < 4; ++q)
                bp[q] = *(const ull*)&hys[cur][dp][tx + 16 * q];   // lane-contiguous
            #pragma unroll
            for (int a = 0; a < 4; ++a)
                #pragma unroll
                for (int b = 0; b < 4; ++b)
                    acc[a][b] = f2_fma(f2_relu(f2_add(ap[a], bp[b])), w2k, acc[a][b]);
        }
        __syncthreads();
    }

    #pragma unroll
    for (int a = 0; a < 4; ++a)
        #pragma unroll
        for (int b = 0; b < 4; ++b)
            out[(i0 + ty + 16 * a) * NY + (j0 + tx + 16 * b)] = f2_sum(acc[a][b]);
}

extern "C" void kernel_launch(void* const* d_in, const int* in_sizes, int n_in,
                              void* d_out, int out_size) {
    const float* x  = (const float*)d_in[0];
    const float* y  = (const float*)d_in[1];
    const float* W1 = (const float*)d_in[2];
    const float* W2 = (const float*)d_in[3];
    // d_in[4] = is_pairwise (int32) — dataset fixes it to 0 (out_size == NX*NY)
    float* out = (float*)d_out;

    dim3 g1(DIM / 64, NX / 64, 2);    // 8 x 16 x 2 = 256 CTAs
    gemm_kernel<<<g1, 256>>>(x, y, W1);

    dim3 g2(NY / 64, NX / 64);        // 16 x 16 = 256 CTAs
    pair_kernel<<<g2, 256>>>(W2, out);
}